// round 1
// baseline (speedup 1.0000x reference)
#include <cuda_runtime.h>

#define DM   2048   // d_model
#define DS   16     // d_state
#define NB   8      // batch
#define LQ   512    // seq
#define NC   8      // chunks
#define LC   64     // chunk length

// ---- scratch (no allocations allowed) ----
__device__ float g_dA  [DM * DS];            // exp(dt*A)
__device__ float g_cb  [DM * DS];            // C * dt * B
__device__ float g_dA64[DM * DS];            // exp(64*dt*A) = dA^64
__device__ float g_end [NC * NB * DM * DS];  // local chunk end states (zero init)
__device__ float g_init[NC * NB * DM * DS];  // state entering each chunk

// ---- packed f32x2 helpers ----
__device__ __forceinline__ unsigned long long pk(float lo, float hi) {
    unsigned long long r;
    asm("mov.b64 %0, {%1, %2};" : "=l"(r) : "f"(lo), "f"(hi));
    return r;
}
__device__ __forceinline__ void upk(unsigned long long v, float& lo, float& hi) {
    asm("mov.b64 {%0, %1}, %2;" : "=f"(lo), "=f"(hi) : "l"(v));
}
__device__ __forceinline__ unsigned long long fma2(unsigned long long a,
                                                   unsigned long long b,
                                                   unsigned long long c) {
    unsigned long long r;
    asm("fma.rn.f32x2 %0, %1, %2, %3;" : "=l"(r) : "l"(a), "l"(b), "l"(c));
    return r;
}
__device__ __forceinline__ unsigned long long mul2(unsigned long long a,
                                                   unsigned long long b) {
    unsigned long long r;
    asm("mul.rn.f32x2 %0, %1, %2;" : "=l"(r) : "l"(a), "l"(b));
    return r;
}

// ---- kernel 0: parameter precompute (32768 threads, one-shot) ----
__global__ void k_pre(const float* __restrict__ A_log,
                      const float* __restrict__ Bm,
                      const float* __restrict__ Cm,
                      const float* __restrict__ log_dt) {
    int i = blockIdx.x * blockDim.x + threadIdx.x;
    if (i >= DM * DS) return;
    int d = i >> 4;
    float dt = expf(log_dt[d]);          // DT_SCALE = 1
    float A  = expf(A_log[i]);
    float u  = dt * A;
    g_dA[i]   = expf(u);
    g_dA64[i] = expf(64.0f * u);
    g_cb[i]   = Cm[i] * (dt * Bm[i]);
}

// ---- phase A: per-(b,d,chunk) local end state, p-form (no dB, no output) ----
__global__ void __launch_bounds__(256)
k_chunk_end(const float* __restrict__ x) {
    int idx = blockIdx.x * 256 + threadIdx.x;   // 131072 threads
    int d = idx & (DM - 1);
    int b = (idx >> 11) & (NB - 1);
    int c = idx >> 14;

    unsigned long long dA2[8];
    const float4* pa = (const float4*)(g_dA + (d << 4));
#pragma unroll
    for (int k = 0; k < 4; k++) {
        float4 v = pa[k];
        dA2[2 * k]     = pk(v.x, v.y);
        dA2[2 * k + 1] = pk(v.z, v.w);
    }

    unsigned long long p2[8];
#pragma unroll
    for (int k = 0; k < 8; k++) p2[k] = 0ull;   // (0.0f, 0.0f)

    const float* xp = x + (size_t)(b * LQ + c * LC) * DM + d;
#pragma unroll 4
    for (int t = 0; t < LC; t++) {
        float xt = xp[0];
        xp += DM;
        unsigned long long xx = pk(xt, xt);
#pragma unroll
        for (int k = 0; k < 8; k++) p2[k] = fma2(dA2[k], p2[k], xx);
    }

    float4* pe = (float4*)(g_end + ((size_t)idx << 4));
#pragma unroll
    for (int k = 0; k < 4; k++) {
        float a0, a1, a2, a3;
        upk(p2[2 * k], a0, a1);
        upk(p2[2 * k + 1], a2, a3);
        pe[k] = make_float4(a0, a1, a2, a3);
    }
}

// ---- phase B: inter-chunk scan over NC=8 (262144 threads) ----
__global__ void k_scan() {
    int idx = blockIdx.x * blockDim.x + threadIdx.x;  // (b,d,n), n fastest
    int n  = idx & 15;
    int bd = idx >> 4;
    int d  = bd & (DM - 1);
    float a64 = g_dA64[(d << 4) | n];
    float h = 0.0f;
#pragma unroll
    for (int c = 1; c < NC; c++) {
        h = fmaf(a64, h, g_end[((c - 1) << 18) + idx]);
        g_init[(c << 18) + idx] = h;   // state entering chunk c
    }
}

// ---- phase C: full scan with correct init + output dot ----
__global__ void __launch_bounds__(256)
k_out(const float* __restrict__ x, float* __restrict__ y) {
    int idx = blockIdx.x * 256 + threadIdx.x;   // 131072 threads
    int d = idx & (DM - 1);
    int b = (idx >> 11) & (NB - 1);
    int c = idx >> 14;

    unsigned long long dA2[8], cb2[8];
    const float4* pa = (const float4*)(g_dA + (d << 4));
    const float4* pc = (const float4*)(g_cb + (d << 4));
#pragma unroll
    for (int k = 0; k < 4; k++) {
        float4 va = pa[k];
        dA2[2 * k]     = pk(va.x, va.y);
        dA2[2 * k + 1] = pk(va.z, va.w);
        float4 vc = pc[k];
        cb2[2 * k]     = pk(vc.x, vc.y);
        cb2[2 * k + 1] = pk(vc.z, vc.w);
    }

    unsigned long long p2[8];
    if (c == 0) {
#pragma unroll
        for (int k = 0; k < 8; k++) p2[k] = 0ull;
    } else {
        const float4* pi = (const float4*)(g_init + ((size_t)idx << 4));
#pragma unroll
        for (int k = 0; k < 4; k++) {
            float4 v = pi[k];
            p2[2 * k]     = pk(v.x, v.y);
            p2[2 * k + 1] = pk(v.z, v.w);
        }
    }

    size_t off = (size_t)(b * LQ + c * LC) * DM + d;
    const float* xp = x + off;
    float*       yp = y + off;

#pragma unroll 4
    for (int t = 0; t < LC; t++) {
        float xt = xp[0];
        xp += DM;
        unsigned long long xx = pk(xt, xt);
#pragma unroll
        for (int k = 0; k < 8; k++) p2[k] = fma2(dA2[k], p2[k], xx);

        unsigned long long acc0 = mul2(cb2[0], p2[0]);
        unsigned long long acc1 = mul2(cb2[1], p2[1]);
#pragma unroll
        for (int k = 2; k < 8; k += 2) {
            acc0 = fma2(cb2[k],     p2[k],     acc0);
            acc1 = fma2(cb2[k + 1], p2[k + 1], acc1);
        }
        float s0, s1, s2, s3;
        upk(acc0, s0, s1);
        upk(acc1, s2, s3);
        yp[0] = (s0 + s1) + (s2 + s3);
        yp += DM;
    }
}

extern "C" void kernel_launch(void* const* d_in, const int* in_sizes, int n_in,
                              void* d_out, int out_size) {
    const float* x      = (const float*)d_in[0];
    const float* A_log  = (const float*)d_in[1];
    const float* B      = (const float*)d_in[2];
    const float* C      = (const float*)d_in[3];
    const float* log_dt = (const float*)d_in[4];
    float* y = (float*)d_out;

    k_pre<<<(DM * DS + 255) / 256, 256>>>(A_log, B, C, log_dt);
    k_chunk_end<<<(NC * NB * DM) / 256, 256>>>(x);
    k_scan<<<(NB * DM * DS) / 256, 256>>>();
    k_out<<<(NC * NB * DM) / 256, 256>>>(x, y);
}

// round 3
// speedup vs baseline: 1.0074x; 1.0074x over previous
#include <cuda_runtime.h>

#define DM   2048   // d_model
#define DS   16     // d_state
#define NB   8      // batch
#define LQ   512    // seq
#define NC   16     // chunks
#define LC   32     // chunk length  (NC*LC == LQ)

#define BDIM 256

// ---- scratch (no allocations allowed) ----
__device__ float g_dA  [DM * DS];            // exp(dt*A)
__device__ float g_cb  [DM * DS];            // C * dt * B
__device__ float g_dAL [DM * DS];            // exp(LC*dt*A) = dA^LC
__device__ float g_end [NC * NB * DM * DS];  // local chunk end states
__device__ float g_init[NC * NB * DM * DS];  // state entering each chunk

// ---- packed f32x2 helpers ----
__device__ __forceinline__ unsigned long long pk(float lo, float hi) {
    unsigned long long r;
    asm("mov.b64 %0, {%1, %2};" : "=l"(r) : "f"(lo), "f"(hi));
    return r;
}
__device__ __forceinline__ void upk(unsigned long long v, float& lo, float& hi) {
    asm("mov.b64 {%0, %1}, %2;" : "=f"(lo), "=f"(hi) : "l"(v));
}
__device__ __forceinline__ unsigned long long fma2(unsigned long long a,
                                                   unsigned long long b,
                                                   unsigned long long c) {
    unsigned long long r;
    asm("fma.rn.f32x2 %0, %1, %2, %3;" : "=l"(r) : "l"(a), "l"(b), "l"(c));
    return r;
}
__device__ __forceinline__ unsigned long long mul2(unsigned long long a,
                                                   unsigned long long b) {
    unsigned long long r;
    asm("mul.rn.f32x2 %0, %1, %2;" : "=l"(r) : "l"(a), "l"(b));
    return r;
}

// ---- kernel 0: parameter precompute (one-shot, tiny) ----
__global__ void k_pre(const float* __restrict__ A_log,
                      const float* __restrict__ Bm,
                      const float* __restrict__ Cm,
                      const float* __restrict__ log_dt) {
    int i = blockIdx.x * blockDim.x + threadIdx.x;
    if (i >= DM * DS) return;
    int d = i >> 4;
    float dt = expf(log_dt[d]);          // DT_SCALE = 1
    float A  = expf(A_log[i]);
    float u  = dt * A;
    g_dA[i]  = expf(u);
    g_dAL[i] = expf((float)LC * u);
    g_cb[i]  = Cm[i] * (dt * Bm[i]);
}

// ---- phase A: per-(c,b,d) local end state, p-form (broadcast x, no output) ----
__global__ void __launch_bounds__(BDIM, 4)
k_chunk_end(const float* __restrict__ x) {
    int idx = blockIdx.x * BDIM + threadIdx.x;  // NC*NB*DM = 262144 threads
    int d = idx & (DM - 1);
    int b = (idx >> 11) & (NB - 1);
    int c = idx >> 14;

    unsigned long long dA2[8];
    const float4* pa = (const float4*)(g_dA + (d << 4));
#pragma unroll
    for (int k = 0; k < 4; k++) {
        float4 v = pa[k];
        dA2[2 * k]     = pk(v.x, v.y);
        dA2[2 * k + 1] = pk(v.z, v.w);
    }

    unsigned long long p2[8];
#pragma unroll
    for (int k = 0; k < 8; k++) p2[k] = 0ull;

    const float* xp = x + (size_t)(b * LQ + c * LC) * DM + d;
#pragma unroll 8
    for (int t = 0; t < LC; t++) {
        float xt = xp[0];
        xp += DM;
        unsigned long long xx = pk(xt, xt);
#pragma unroll
        for (int k = 0; k < 8; k++) p2[k] = fma2(dA2[k], p2[k], xx);
    }

    float4* pe = (float4*)(g_end + ((size_t)idx << 4));
#pragma unroll
    for (int k = 0; k < 4; k++) {
        float a0, a1, a2, a3;
        upk(p2[2 * k], a0, a1);
        upk(p2[2 * k + 1], a2, a3);
        pe[k] = make_float4(a0, a1, a2, a3);
    }
}

// ---- phase B: inter-chunk scan over NC chunks (tiny) ----
__global__ void k_scan() {
    int idx = blockIdx.x * blockDim.x + threadIdx.x;  // NB*DM*DS = 262144
    int n  = idx & 15;
    int bd = idx >> 4;
    int d  = bd & (DM - 1);
    float aL = g_dAL[(d << 4) | n];
    float h = 0.0f;
#pragma unroll
    for (int c = 1; c < NC; c++) {
        h = fmaf(aL, h, g_end[((c - 1) << 18) + idx]);
        g_init[(c << 18) + idx] = h;   // state entering chunk c
    }
}

// ---- phase C: full scan with correct init + output dot ----
__global__ void __launch_bounds__(BDIM, 4)
k_out(const float* __restrict__ x, float* __restrict__ y) {
    int idx = blockIdx.x * BDIM + threadIdx.x;  // 262144 threads
    int d = idx & (DM - 1);
    int b = (idx >> 11) & (NB - 1);
    int c = idx >> 14;

    unsigned long long dA2[8], cb2[8];
    const float4* pa = (const float4*)(g_dA + (d << 4));
    const float4* pc = (const float4*)(g_cb + (d << 4));
#pragma unroll
    for (int k = 0; k < 4; k++) {
        float4 va = pa[k];
        dA2[2 * k]     = pk(va.x, va.y);
        dA2[2 * k + 1] = pk(va.z, va.w);
        float4 vc = pc[k];
        cb2[2 * k]     = pk(vc.x, vc.y);
        cb2[2 * k + 1] = pk(vc.z, vc.w);
    }

    unsigned long long p2[8];
    if (c == 0) {
#pragma unroll
        for (int k = 0; k < 8; k++) p2[k] = 0ull;
    } else {
        const float4* pi = (const float4*)(g_init + ((size_t)idx << 4));
#pragma unroll
        for (int k = 0; k < 4; k++) {
            float4 v = pi[k];
            p2[2 * k]     = pk(v.x, v.y);
            p2[2 * k + 1] = pk(v.z, v.w);
        }
    }

    size_t off = (size_t)(b * LQ + c * LC) * DM + d;
    const float* xp = x + off;
    float*       yp = y + off;

#pragma unroll 8
    for (int t = 0; t < LC; t++) {
        float xt = xp[0];
        xp += DM;
        unsigned long long xx = pk(xt, xt);
#pragma unroll
        for (int k = 0; k < 8; k++) p2[k] = fma2(dA2[k], p2[k], xx);

        unsigned long long acc0 = mul2(cb2[0], p2[0]);
        unsigned long long acc1 = mul2(cb2[1], p2[1]);
#pragma unroll
        for (int k = 2; k < 8; k += 2) {
            acc0 = fma2(cb2[k],     p2[k],     acc0);
            acc1 = fma2(cb2[k + 1], p2[k + 1], acc1);
        }
        float s0, s1, s2, s3;
        upk(acc0, s0, s1);
        upk(acc1, s2, s3);
        yp[0] = (s0 + s1) + (s2 + s3);
        yp += DM;
    }
}

extern "C" void kernel_launch(void* const* d_in, const int* in_sizes, int n_in,
                              void* d_out, int out_size) {
    const float* x      = (const float*)d_in[0];
    const float* A_log  = (const float*)d_in[1];
    const float* B      = (const float*)d_in[2];
    const float* C      = (const float*)d_in[3];
    const float* log_dt = (const float*)d_in[4];
    float* y = (float*)d_out;

    k_pre<<<(DM * DS + 255) / 256, 256>>>(A_log, B, C, log_dt);
    k_chunk_end<<<(NC * NB * DM) / BDIM, BDIM>>>(x);
    k_scan<<<(NB * DM * DS) / 256, 256>>>();
    k_out<<<(NC * NB * DM) / BDIM, BDIM>>>(x, y);
}

// round 4
// speedup vs baseline: 1.0977x; 1.0896x over previous
#include <cuda_runtime.h>

#define DM   2048   // d_model
#define DS   16     // d_state
#define NB   8      // batch
#define LQ   512    // seq
#define NC   16     // chunks
#define LC   32     // chunk length (NC*LC == LQ)

#define BDIM 256
#define HS   8      // states per thread (half of DS)

// scratch layout: [half][c][b][d][HS]  (fully coalesced for all phases)
#define SLAB (NB * DM * HS)              // floats per (half,c) slab = 131072
__device__ float g_dA  [DM * DS];        // exp(dt*A)
__device__ float g_cb  [DM * DS];        // C * dt * B
__device__ float g_dAL [DM * DS];        // exp(LC*dt*A) = dA^LC
__device__ float g_end [2 * NC * SLAB];  // local chunk end states
__device__ float g_init[2 * NC * SLAB];  // state entering each chunk

// ---- packed f32x2 helpers ----
__device__ __forceinline__ unsigned long long pk(float lo, float hi) {
    unsigned long long r;
    asm("mov.b64 %0, {%1, %2};" : "=l"(r) : "f"(lo), "f"(hi));
    return r;
}
__device__ __forceinline__ void upk(unsigned long long v, float& lo, float& hi) {
    asm("mov.b64 {%0, %1}, %2;" : "=f"(lo), "=f"(hi) : "l"(v));
}
__device__ __forceinline__ unsigned long long fma2(unsigned long long a,
                                                   unsigned long long b,
                                                   unsigned long long c) {
    unsigned long long r;
    asm("fma.rn.f32x2 %0, %1, %2, %3;" : "=l"(r) : "l"(a), "l"(b), "l"(c));
    return r;
}
__device__ __forceinline__ unsigned long long mul2(unsigned long long a,
                                                   unsigned long long b) {
    unsigned long long r;
    asm("mul.rn.f32x2 %0, %1, %2;" : "=l"(r) : "l"(a), "l"(b));
    return r;
}

// ---- kernel 0: parameter precompute (one-shot, tiny) ----
__global__ void k_pre(const float* __restrict__ A_log,
                      const float* __restrict__ Bm,
                      const float* __restrict__ Cm,
                      const float* __restrict__ log_dt) {
    int i = blockIdx.x * blockDim.x + threadIdx.x;
    if (i >= DM * DS) return;
    int d = i >> 4;
    float dt = expf(log_dt[d]);          // DT_SCALE = 1
    float A  = expf(A_log[i]);
    float u  = dt * A;
    g_dA[i]  = expf(u);
    g_dAL[i] = expf((float)LC * u);
    g_cb[i]  = Cm[i] * (dt * Bm[i]);
}

// ---- phase A: local chunk end states, split-state (HS per thread) ----
__global__ void __launch_bounds__(BDIM, 6)
k_chunk_end(const float* __restrict__ x) {
    int tid  = blockIdx.x * BDIM + threadIdx.x;   // 2*NC*NB*DM = 524288 threads
    int lane = threadIdx.x & 31;
    int half = lane >> 4;
    int pidx = (tid >> 5) * 16 + (lane & 15);     // (c,b,d) pair index
    int d = pidx & (DM - 1);
    int b = (pidx >> 11) & (NB - 1);
    int c = pidx >> 14;

    unsigned long long dA2[4];
    const float4* pa = (const float4*)(g_dA + (d << 4) + half * HS);
#pragma unroll
    for (int k = 0; k < 2; k++) {
        float4 v = pa[k];
        dA2[2 * k]     = pk(v.x, v.y);
        dA2[2 * k + 1] = pk(v.z, v.w);
    }

    unsigned long long p2[4];
#pragma unroll
    for (int k = 0; k < 4; k++) p2[k] = 0ull;

    const float* xp = x + (size_t)(b * LQ + c * LC) * DM + d;
#pragma unroll 8
    for (int t = 0; t < LC; t++) {
        float xt = xp[0];
        xp += DM;
        unsigned long long xx = pk(xt, xt);
#pragma unroll
        for (int k = 0; k < 4; k++) p2[k] = fma2(dA2[k], p2[k], xx);
    }

    // store: [half][c][b][d][HS]
    size_t e_idx = ((size_t)(half * NC + c) * NB + b) * DM * HS + (size_t)d * HS;
    float4* pe = (float4*)(g_end + e_idx);
#pragma unroll
    for (int k = 0; k < 2; k++) {
        float a0, a1, a2, a3;
        upk(p2[2 * k], a0, a1);
        upk(p2[2 * k + 1], a2, a3);
        pe[k] = make_float4(a0, a1, a2, a3);
    }
}

// ---- phase B: inter-chunk scan over NC chunks (tiny) ----
__global__ void k_scan() {
    int tid = blockIdx.x * blockDim.x + threadIdx.x;   // 2*NB*DM*HS = 262144
    int j    = tid & (HS - 1);
    int d    = (tid >> 3) & (DM - 1);
    int b    = (tid >> 14) & (NB - 1);
    int half = tid >> 17;
    int n    = half * HS + j;
    float aL = g_dAL[(d << 4) | n];

    size_t base = ((size_t)(half * NC) * NB + b) * DM * HS + (size_t)d * HS + j;
    float h = 0.0f;
#pragma unroll
    for (int c = 1; c < NC; c++) {
        h = fmaf(aL, h, g_end[base + (size_t)(c - 1) * SLAB]);
        g_init[base + (size_t)c * SLAB] = h;
    }
}

// ---- phase C: full scan with correct init + output dot, split-state ----
__global__ void __launch_bounds__(BDIM, 5)
k_out(const float* __restrict__ x, float* __restrict__ y) {
    int tid  = blockIdx.x * BDIM + threadIdx.x;   // 524288 threads
    int lane = threadIdx.x & 31;
    int half = lane >> 4;
    int pidx = (tid >> 5) * 16 + (lane & 15);
    int d = pidx & (DM - 1);
    int b = (pidx >> 11) & (NB - 1);
    int c = pidx >> 14;

    unsigned long long dA2[4], cb2[4];
    const float4* pa = (const float4*)(g_dA + (d << 4) + half * HS);
    const float4* pc = (const float4*)(g_cb + (d << 4) + half * HS);
#pragma unroll
    for (int k = 0; k < 2; k++) {
        float4 va = pa[k];
        dA2[2 * k]     = pk(va.x, va.y);
        dA2[2 * k + 1] = pk(va.z, va.w);
        float4 vc = pc[k];
        cb2[2 * k]     = pk(vc.x, vc.y);
        cb2[2 * k + 1] = pk(vc.z, vc.w);
    }

    unsigned long long p2[4];
    if (c == 0) {
#pragma unroll
        for (int k = 0; k < 4; k++) p2[k] = 0ull;
    } else {
        size_t e_idx = ((size_t)(half * NC + c) * NB + b) * DM * HS + (size_t)d * HS;
        const float4* pi = (const float4*)(g_init + e_idx);
#pragma unroll
        for (int k = 0; k < 2; k++) {
            float4 v = pi[k];
            p2[2 * k]     = pk(v.x, v.y);
            p2[2 * k + 1] = pk(v.z, v.w);
        }
    }

    size_t off = (size_t)(b * LQ + c * LC) * DM + d;
    const float* xp = x + off;
    float*       yp = y + off;

#pragma unroll 8
    for (int t = 0; t < LC; t++) {
        float xt = xp[0];
        xp += DM;
        unsigned long long xx = pk(xt, xt);
#pragma unroll
        for (int k = 0; k < 4; k++) p2[k] = fma2(dA2[k], p2[k], xx);

        unsigned long long acc0 = mul2(cb2[0], p2[0]);
        unsigned long long acc1 = mul2(cb2[1], p2[1]);
        acc0 = fma2(cb2[2], p2[2], acc0);
        acc1 = fma2(cb2[3], p2[3], acc1);
        float s0, s1, s2, s3;
        upk(acc0, s0, s1);
        upk(acc1, s2, s3);
        float s = (s0 + s1) + (s2 + s3);
        s += __shfl_xor_sync(0xffffffffu, s, 16);
        if (half == 0) yp[0] = s;
        yp += DM;
    }
}

extern "C" void kernel_launch(void* const* d_in, const int* in_sizes, int n_in,
                              void* d_out, int out_size) {
    const float* x      = (const float*)d_in[0];
    const float* A_log  = (const float*)d_in[1];
    const float* B      = (const float*)d_in[2];
    const float* C      = (const float*)d_in[3];
    const float* log_dt = (const float*)d_in[4];
    float* y = (float*)d_out;

    k_pre<<<(DM * DS + 255) / 256, 256>>>(A_log, B, C, log_dt);
    k_chunk_end<<<(2 * NC * NB * DM) / BDIM, BDIM>>>(x);
    k_scan<<<(2 * NB * DM * HS) / 256, 256>>>();
    k_out<<<(2 * NC * NB * DM) / BDIM, BDIM>>>(x, y);
}